// round 10
// baseline (speedup 1.0000x reference)
#include <cuda_runtime.h>

#define IN_DIM   8192
#define OUT_DIM  16384
#define TOPK     327
#define ROW_SPLITS 37                 // 16 * 37 = 592 = 4 * 148 SMs
#define ROWS_PER_SPLIT 222            // ceil(8192 / 37)
#define COL_BLOCKS 16
#define NBLOCKS  (COL_BLOCKS * ROW_SPLITS)   // 592
#define CNT_ONE  (1u << 20)
#define VAL_MASK 0xFFFFFu

__device__ unsigned g_overlap[OUT_DIM];   // [counter:12 | value:20]; zero at load & after finalize
__device__ int      g_hist[IN_DIM + 1];   // zero at load & after finalize
__device__ int      g_done;               // gemv-phase completion counter
__device__ int      g_T, g_R;
__device__ int      g_Tready;
__device__ int      g_tieseg[16];
__device__ int      g_cnt1, g_cnt2;

__device__ __forceinline__ int warp_incl_scan(int v) {
    int lane = threadIdx.x & 31;
#pragma unroll
    for (int o = 1; o < 32; o <<= 1) {
        int n = __shfl_up_sync(0xffffffffu, v, o);
        if (lane >= o) v += n;
    }
    return v;
}

// ---------------------------------------------------------------------------
// ONE kernel: binarized GEMV (all 592 blocks) + fused histogram + in-kernel
// grid rendezvous + threshold + exact jax.lax.top_k output (17 blocks).
// round(p) for p ~ U[0,1) under round-half-even == (p > 0.5f).
// ---------------------------------------------------------------------------
__global__ void __launch_bounds__(256, 4)
fused_kernel(const float* __restrict__ p, const int* __restrict__ x,
             float* __restrict__ out) {
    __shared__ int s_act[ROWS_PER_SPLIT];
    __shared__ int s_hist[IN_DIM + 1];    // used by threshold block only
    __shared__ int s_scan[256];
    __shared__ int s_w[8];
    __shared__ int s_wexc[8];
    __shared__ int s_na, s_T, s_R, s_total;

    int t    = threadIdx.x;
    int lane = t & 31;
    int w    = t >> 5;
    int bid  = blockIdx.y * COL_BLOCKS + blockIdx.x;

    // ======================= Phase 1: GEMV =======================
    {
        int r0 = blockIdx.y * ROWS_PER_SPLIT;
        int r1 = min(r0 + ROWS_PER_SPLIT, IN_DIM);
        int n  = r1 - r0;

        int flag = 0;
        if (t < n) flag = (x[r0 + t] != 0);
        unsigned m = __ballot_sync(0xffffffffu, flag);
        int pos = __popc(m & ((1u << lane) - 1u));
        if (lane == 0) s_w[w] = __popc(m);
        __syncthreads();
        if (t < 8) {
            int v = s_w[t];
            int inc = v;
#pragma unroll
            for (int o = 1; o < 8; o <<= 1) {
                int u = __shfl_up_sync(0xffu, inc, o);
                if (t >= o) inc += u;
            }
            s_w[t] = inc - v;              // exclusive base (overwrites count)
            if (t == 7) s_na = inc;
        }
        __syncthreads();
        if (flag) s_act[s_w[w] + pos] = r0 + t;
        __syncthreads();

        int na = s_na;
        int col = (blockIdx.x * blockDim.x + t) * 4;
        const float4* pc = reinterpret_cast<const float4*>(p + col);

        unsigned c0 = 0, c1 = 0, c2 = 0, c3 = 0;
        int r = 0;
        for (; r + 8 <= na; r += 8) {
            float4 v[8];
#pragma unroll
            for (int u = 0; u < 8; u++)
                v[u] = __ldcs(pc + (size_t)s_act[r + u] * (OUT_DIM / 4));
#pragma unroll
            for (int u = 0; u < 8; u++) {
                c0 += (v[u].x > 0.5f);
                c1 += (v[u].y > 0.5f);
                c2 += (v[u].z > 0.5f);
                c3 += (v[u].w > 0.5f);
            }
        }
        for (; r < na; r++) {
            float4 v0 = __ldcs(pc + (size_t)s_act[r] * (OUT_DIM / 4));
            c0 += (v0.x > 0.5f);
            c1 += (v0.y > 0.5f);
            c2 += (v0.z > 0.5f);
            c3 += (v0.w > 0.5f);
        }

        unsigned cc[4] = {c0, c1, c2, c3};
#pragma unroll
        for (int u = 0; u < 4; u++) {
            unsigned old = atomicAdd(&g_overlap[col + u], CNT_ONE + cc[u]);
            if ((old >> 20) == (ROW_SPLITS - 1)) {
                int final_v = (int)((old & VAL_MASK) + cc[u]);
                atomicAdd(&g_hist[final_v], 1);
            }
        }
    }

    // all atomics of this block have completed (they returned values)
    __syncthreads();
    if (t == 0) atomicAdd(&g_done, 1);

    if (bid > 16) return;                 // 575 blocks retire, freeing SMs

    // ======================= Phase 2: finalize =======================
    if (bid == 16) {
        // ---- threshold block ----
        if (t == 0) {
            while (atomicAdd(&g_done, 0) < NBLOCKS) __nanosleep(64);
        }
        __syncthreads();
        __threadfence();

        for (int i = t; i <= IN_DIM; i += 256) s_hist[i] = g_hist[i];
        __syncthreads();

        // thread t owns bins [32t, 32t+31]; thread 255 also owns bin 8192
        int b0 = t * 32;
        int csum = 0;
#pragma unroll
        for (int k = 0; k < 32; k++) csum += s_hist[b0 + k];
        if (t == 255) csum += s_hist[IN_DIM];

        s_scan[255 - t] = csum;            // reversed → prefix scan = suffix scan
        __syncthreads();
        {
            int v = s_scan[t];
            int inc = warp_incl_scan(v);
            if (lane == 31) s_w[w] = inc;
            __syncthreads();
            if (w == 0) {
                int wv = (lane < 8) ? s_w[lane] : 0;
                int winc = warp_incl_scan(wv);
                if (lane < 8) s_w[lane] = winc;
            }
            __syncthreads();
            int add = (w > 0) ? s_w[w - 1] : 0;
            s_scan[t] = inc + add;
        }
        __syncthreads();

        int above = (t == 255) ? 0 : s_scan[254 - t];
        {
            int running = above;
            int top = (t == 255) ? IN_DIM : (b0 + 31);
            for (int v = top; v >= b0; v--) {
                int prev = running;            // count(> v)
                running += s_hist[v];          // count(>= v)
                if (prev < TOPK && running >= TOPK) {
                    g_T = v;
                    g_R = TOPK - prev;
                }
            }
        }
        __syncthreads();
        __threadfence();
        if (t == 0) atomicExch(&g_Tready, 1);

        for (int i = t; i <= IN_DIM; i += 256) g_hist[i] = 0;

        if (t == 0) {
            while (atomicAdd(&g_cnt2, 0) < 16) __nanosleep(64);
            atomicExch(&g_Tready, 0);
            atomicExch(&g_cnt1, 0);
            atomicExch(&g_cnt2, 0);
            atomicExch(&g_done, 0);
        }
    } else {
        // ---- worker block: columns [bid*1024, bid*1024+1024) ----
        if (t == 0) {
            while (atomicAdd(&g_done, 0) < NBLOCKS) __nanosleep(64);
        }
        __syncthreads();
        __threadfence();

        int colbase = bid * 1024;
        int ovv[4];
#pragma unroll
        for (int s = 0; s < 4; s++)
            ovv[s] = (int)(g_overlap[colbase + s * 256 + t] & VAL_MASK);

        if (t == 0) {
            while (atomicAdd(&g_Tready, 0) == 0) __nanosleep(32);
            __threadfence();
            s_T = g_T;
            s_R = g_R;
        }
        __syncthreads();
        int T = s_T;
        int R = s_R;

        // ordered tie ranks: 4 passes over contiguous 256-column chunks
        unsigned lt = (1u << lane) - 1u;
        int local_base = 0;
        int rankl[4];
        unsigned flg = 0;
#pragma unroll
        for (int s = 0; s < 4; s++) {
            int flag = (ovv[s] == T);
            unsigned m = __ballot_sync(0xffffffffu, flag);
            if (lane == 0) s_w[w] = __popc(m);
            __syncthreads();
            if (w == 0) {
                int wv = (lane < 8) ? s_w[lane] : 0;
                int inc = warp_incl_scan(wv);
                if (lane < 8) s_wexc[lane] = inc - wv;
                if (lane == 7) s_total = inc;
            }
            __syncthreads();
            rankl[s] = local_base + s_wexc[w] + __popc(m & lt);
            local_base += s_total;
            if (flag) flg |= (1u << s);
            __syncthreads();
        }

        // cross-block exclusive base over segment tie counts
        if (t == 0) {
            g_tieseg[bid] = local_base;
            __threadfence();
            atomicAdd(&g_cnt1, 1);
            while (atomicAdd(&g_cnt1, 0) < 16) __nanosleep(32);
            __threadfence();
        }
        __syncthreads();
        if (t < 16) s_scan[t] = g_tieseg[t];
        __syncthreads();
        int gbase = 0;
        for (int j = 0; j < bid; j++) gbase += s_scan[j];

#pragma unroll
        for (int s = 0; s < 4; s++) {
            int col = colbase + s * 256 + t;
            float val = 0.0f;
            if (ovv[s] > T) val = 1.0f;
            else if (((flg >> s) & 1) && (gbase + rankl[s]) < R) val = 1.0f;
            out[col] = val;
            g_overlap[col] = 0u;           // reset accumulator slice
        }
        __threadfence();
        __syncthreads();
        if (t == 0) atomicAdd(&g_cnt2, 1);
    }
}

extern "C" void kernel_launch(void* const* d_in, const int* in_sizes, int n_in,
                              void* d_out, int out_size) {
    const int*   x = (const int*)d_in[0];
    const float* p = (const float*)d_in[1];
    if (in_sizes[0] != IN_DIM) {
        x = (const int*)d_in[1];
        p = (const float*)d_in[0];
    }
    float* out = (float*)d_out;

    dim3 grid(COL_BLOCKS, ROW_SPLITS);
    fused_kernel<<<grid, 256>>>(p, x, out);
}